// round 2
// baseline (speedup 1.0000x reference)
#include <cuda_runtime.h>
#include <cuda_bf16.h>
#include <math.h>

// Problem constants (fixed by the dataset):
//   TLEN=128, C=64, H=W=28 -> HW=784, batch B=8, V=16 frames/sample, K(topk)=4
// Dead-code analysis: sim_n <= 0 < 0.05 everywhere => thresholded to -100 everywhere
// => top_k indices are always [0,1,2,3] (stable tie-break). Graph is a fixed constant.

#define BV 8
#define VV 16
#define CC 64
#define HWP 784
#define KDIM 192          // 3 taps * 64 channels
#define BN_EPS 1e-5f

// ------------------------- scratch (static device memory; no allocs) ------
__device__ float g_w2[KDIM * CC];     // fused down-conv*BN*gcn weights, [k][co]
__device__ float g_b2[CC];            // fused bias (incl. gcn_b)
__device__ float g_wu[KDIM * CC];     // up-conv*BN weights, [k][co]
__device__ float g_bu[CC];
__device__ float g_mid[BV * VV * CC * HWP];   // intermediate, layout [t=b*16+v][c][p]
__device__ float g_fix[BV * 61 * CC];         // fixed-up node values

// ------------------------- prep: fold down BN + gcn GEMM into one conv ----
__global__ void prep_down_k(const float* __restrict__ G,  const float* __restrict__ Wd,
                            const float* __restrict__ dg, const float* __restrict__ db,
                            const float* __restrict__ dm, const float* __restrict__ dvar,
                            const float* __restrict__ gb) {
    int idx = blockIdx.x * 256 + threadIdx.x;   // 12288 weight elems
    if (idx < KDIM * CC) {
        int co = idx & 63;
        int k  = idx >> 6;
        int cj = k & 63;
        int dt = k >> 6;
        float acc = 0.f;
        #pragma unroll 8
        for (int ci = 0; ci < CC; ci++) {
            float s = dg[ci] * rsqrtf(dvar[ci] + BN_EPS);
            acc += G[co * CC + ci] * s * Wd[(ci * CC + cj) * 3 + dt];
        }
        g_w2[k * CC + co] = acc;
    }
    if (idx < CC) {
        float acc = gb[idx];
        #pragma unroll 8
        for (int ci = 0; ci < CC; ci++) {
            float s = dg[ci] * rsqrtf(dvar[ci] + BN_EPS);
            acc += G[idx * CC + ci] * (db[ci] - dm[ci] * s);
        }
        g_b2[idx] = acc;
    }
}

__global__ void prep_up_k(const float* __restrict__ Wu, const float* __restrict__ ug,
                          const float* __restrict__ ub, const float* __restrict__ um,
                          const float* __restrict__ uvar) {
    int idx = blockIdx.x * 256 + threadIdx.x;
    if (idx < KDIM * CC) {
        int co = idx & 63;
        int k  = idx >> 6;
        int ci = k & 63;
        int dt = k >> 6;
        float su = ug[co] * rsqrtf(uvar[co] + BN_EPS);
        g_wu[k * CC + co] = su * Wu[(co * CC + ci) * 3 + dt];
    }
    if (idx < CC) {
        float su = ug[idx] * rsqrtf(uvar[idx] + BN_EPS);
        g_bu[idx] = ub[idx] - um[idx] * su;
    }
}

// ------------------------- main conv: 3-tap temporal, full channel mix ----
// out[t=b*16+v][co][p] = bias[co] + sum_{dt,ci} Wk[dt*64+ci][co] * in[b*16+v+dt-1][ci][p]
// Block: one (b,v), p-tile of 64.  256 threads, 4co x 4p micro-tile per thread.
__global__ void conv3_kernel(const float* __restrict__ in, const float* __restrict__ wk,
                             const float* __restrict__ bias, float* __restrict__ out) {
    extern __shared__ float sm[];
    float* Ws = sm;                 // [KDIM][64] weights
    float* Xs = sm + KDIM * CC;     // [KDIM][64] input slab
    const int tid = threadIdx.x;
    const int p0 = blockIdx.x * 64;
    const int v = blockIdx.y, b = blockIdx.z;

    // stage weights (12288 floats = 3072 float4)
    float4* Ws4 = (float4*)Ws;
    const float4* wk4 = (const float4*)wk;
    #pragma unroll
    for (int i = 0; i < 12; i++) Ws4[tid + i * 256] = wk4[tid + i * 256];

    // stage input slab: rows k=(dt,ci) from frame v+dt-1 (zero pad)
    float4* Xs4 = (float4*)Xs;
    #pragma unroll
    for (int i = 0; i < 12; i++) {
        int j = tid + i * 256;
        int k = j >> 4, q = j & 15;
        int dt = k >> 6, ci = k & 63;
        int f = v + dt - 1;
        int p = p0 + q * 4;
        float4 val = make_float4(0.f, 0.f, 0.f, 0.f);
        if (f >= 0 && f < VV && p < HWP)
            val = *(const float4*)(in + (((size_t)(b * VV + f) * CC + ci) * HWP + p));
        Xs4[j] = val;
    }
    __syncthreads();

    const int pg = tid & 15;    // p sub-tile (4 positions)
    const int cg = tid >> 4;    // co sub-tile (4 channels)
    float acc[4][4];
    #pragma unroll
    for (int i = 0; i < 4; i++)
        #pragma unroll
        for (int j = 0; j < 4; j++) acc[i][j] = 0.f;

    const float4* Xr = (const float4*)Xs;
    const float4* Wr = (const float4*)Ws;
    #pragma unroll 8
    for (int k = 0; k < KDIM; k++) {
        float4 xv = Xr[k * 16 + pg];
        float4 wv = Wr[k * 16 + cg];
        acc[0][0] += wv.x * xv.x; acc[0][1] += wv.x * xv.y; acc[0][2] += wv.x * xv.z; acc[0][3] += wv.x * xv.w;
        acc[1][0] += wv.y * xv.x; acc[1][1] += wv.y * xv.y; acc[1][2] += wv.y * xv.z; acc[1][3] += wv.y * xv.w;
        acc[2][0] += wv.z * xv.x; acc[2][1] += wv.z * xv.y; acc[2][2] += wv.z * xv.z; acc[2][3] += wv.z * xv.w;
        acc[3][0] += wv.w * xv.x; acc[3][1] += wv.w * xv.y; acc[3][2] += wv.w * xv.z; acc[3][3] += wv.w * xv.w;
    }

    int p = p0 + pg * 4;
    if (p < HWP) {
        #pragma unroll
        for (int i = 0; i < 4; i++) {
            int c = cg * 4 + i;
            float bv = bias[c];
            float4 o = make_float4(acc[i][0] + bv, acc[i][1] + bv, acc[i][2] + bv, acc[i][3] + bv);
            *(float4*)(out + (((size_t)(b * VV + v) * CC + c) * HWP + p)) = o;
        }
    }
}

// ------------------------- GCN fixup for the 61 special nodes per sample --
__device__ __forceinline__ float degf(int v, int p) {
    if (p != 0) return 2.f;
    if (v == 0) return 5.f;
    if (v == 15) return 2.f;
    return 6.f;
}

__global__ void fixup_gather(const float* __restrict__ mid, const float* __restrict__ gb,
                             float* __restrict__ fix) {
    int col = blockIdx.x;   // 0..60
    int b = blockIdx.y;
    int c = threadIdx.x;    // 0..63
    int v, p;
    if (col < 16) { v = col; p = 0; }
    else { int j = col - 16; v = 1 + j / 3; p = 1 + j % 3; }
    float gbias = gb[c];
    // xw = mid - gcn_b  (mid folded gcn_b into the conv bias)
#define XW(vv, pp) (mid[(((size_t)(b * VV + (vv)) * CC) + c) * HWP + (pp)] - gbias)
    float dc = degf(v, p);
    float sum = XW(v, p) * rsqrtf(dc);
    if (p == 0) {
        if (v <= 14) {
            sum += XW(v + 1, 0) * rsqrtf(degf(v + 1, 0));
            sum += (XW(v + 1, 1) + XW(v + 1, 2) + XW(v + 1, 3)) * rsqrtf(2.f);
        }
        if (v >= 1) sum += XW(v - 1, 0) * rsqrtf(degf(v - 1, 0));
    } else {
        sum += XW(v - 1, 0) * rsqrtf(degf(v - 1, 0));
    }
#undef XW
    fix[(b * 61 + col) * CC + c] = sum * rsqrtf(dc) + gbias;
}

__global__ void fixup_scatter(const float* __restrict__ fix, float* __restrict__ mid) {
    int col = blockIdx.x;
    int b = blockIdx.y;
    int c = threadIdx.x;
    int v, p;
    if (col < 16) { v = col; p = 0; }
    else { int j = col - 16; v = 1 + j / 3; p = 1 + j % 3; }
    mid[(((size_t)(b * VV + v) * CC) + c) * HWP + p] = fix[(b * 61 + col) * CC + c];
}

// ------------------------- launch ----------------------------------------
extern "C" void kernel_launch(void* const* d_in, const int* in_sizes, int n_in,
                              void* d_out, int out_size) {
    const float* x          = (const float*)d_in[0];
    // d_in[1] = batch (int, ==8)
    const float* down_w     = (const float*)d_in[2];
    const float* down_gamma = (const float*)d_in[3];
    const float* down_beta  = (const float*)d_in[4];
    const float* down_mean  = (const float*)d_in[5];
    const float* down_var   = (const float*)d_in[6];
    const float* gcn_w      = (const float*)d_in[7];
    const float* gcn_b      = (const float*)d_in[8];
    const float* up_w       = (const float*)d_in[9];
    const float* up_gamma   = (const float*)d_in[10];
    const float* up_beta    = (const float*)d_in[11];
    const float* up_mean    = (const float*)d_in[12];
    const float* up_var     = (const float*)d_in[13];
    float* out = (float*)d_out;

    float *w2, *b2, *wu, *bu, *mid, *fix;
    cudaGetSymbolAddress((void**)&w2,  g_w2);
    cudaGetSymbolAddress((void**)&b2,  g_b2);
    cudaGetSymbolAddress((void**)&wu,  g_wu);
    cudaGetSymbolAddress((void**)&bu,  g_bu);
    cudaGetSymbolAddress((void**)&mid, g_mid);
    cudaGetSymbolAddress((void**)&fix, g_fix);

    const int smem = 2 * KDIM * CC * sizeof(float);   // 96 KB
    cudaFuncSetAttribute(conv3_kernel, cudaFuncAttributeMaxDynamicSharedMemorySize, smem);

    prep_down_k<<<48, 256>>>(gcn_w, down_w, down_gamma, down_beta, down_mean, down_var, gcn_b);
    prep_up_k<<<48, 256>>>(up_w, up_gamma, up_beta, up_mean, up_var);

    // conv1: x -> mid   (down conv + BN + gcn GEMM + gcn bias, all fused)
    conv3_kernel<<<dim3(13, VV, BV), 256, smem>>>(x, w2, b2, mid);

    // GCN graph fixup on the 61 special nodes per sample
    fixup_gather<<<dim3(61, BV), CC>>>(mid, gcn_b, fix);
    fixup_scatter<<<dim3(61, BV), CC>>>(fix, mid);

    // conv2: mid -> out (up conv + BN), output layout matches [tlen, c, h, w]
    conv3_kernel<<<dim3(13, VV, BV), 256, smem>>>(mid, wu, bu, out);
}